// round 5
// baseline (speedup 1.0000x reference)
#include <cuda_runtime.h>
#include <cuda_bf16.h>
#include <math.h>

// ---------------------------------------------------------------------------
// Problem constants (B=1, S=4096, DIM=1536, HEADS=12, HEAD_DIM=128)
// ---------------------------------------------------------------------------
#define SEQ    4096
#define DIM    1536
#define NHEADS 12
#define HDIM   128
#define EPS    1e-6f

// Scratch (allocation-free rule: __device__ globals)
__device__ float g_q[SEQ * DIM];
__device__ float g_k[SEQ * DIM];
__device__ float g_v[SEQ * DIM];
__device__ float g_attn[SEQ * DIM];
__device__ float g_kf[SEQ * DIM];        // K fragment-order: [h][s][f(d)]
__device__ float g_vf[SEQ * DIM];        // V fragment-order: [h][kb][kt][d][slot]
__device__ float g_trig[SEQ * 64 * 2];   // interleaved cos, sin per (pos, pair)

// ---------------------------------------------------------------------------
// Helpers
// ---------------------------------------------------------------------------
__device__ __forceinline__ float to_tf32(float x) {
    unsigned u;
    asm("cvt.rna.tf32.f32 %0, %1;" : "=r"(u) : "f"(x));
    return __uint_as_float(u);
}
__device__ __forceinline__ unsigned fu(float x) { return __float_as_uint(x); }

__device__ __forceinline__ void mma_tf32(float* d, const unsigned* a,
                                         unsigned b0, unsigned b1) {
    asm volatile(
        "mma.sync.aligned.m16n8k8.row.col.f32.tf32.tf32.f32 "
        "{%0,%1,%2,%3}, {%4,%5,%6,%7}, {%8,%9}, {%0,%1,%2,%3};\n"
        : "+f"(d[0]), "+f"(d[1]), "+f"(d[2]), "+f"(d[3])
        : "r"(a[0]), "r"(a[1]), "r"(a[2]), "r"(a[3]), "r"(b0), "r"(b1));
}

__device__ __forceinline__ void cp16(float* smem_dst, const float* gsrc) {
    unsigned s = (unsigned)__cvta_generic_to_shared(smem_dst);
    asm volatile("cp.async.cg.shared.global [%0], [%1], 16;\n" :: "r"(s), "l"(gsrc));
}
__device__ __forceinline__ void cp_commit() {
    asm volatile("cp.async.commit_group;\n");
}
template <int N>
__device__ __forceinline__ void cp_wait() {
    asm volatile("cp.async.wait_group %0;\n" :: "n"(N));
}

// fragment-order column permutation within a 128-wide head
__device__ __forceinline__ int fperm(int d) {
    return (d >> 3) * 8 + (d & 3) * 2 + ((d >> 2) & 1);
}

// ---------------------------------------------------------------------------
// RoPE trig table with double-precision range reduction.
// ---------------------------------------------------------------------------
__global__ __launch_bounds__(256) void trig_kernel(const float* __restrict__ freqs) {
    int idx = blockIdx.x * blockDim.x + threadIdx.x;
    if (idx >= SEQ * 64) return;
    double a = (double)freqs[idx];
    double s, c;
    sincos(a, &s, &c);
    g_trig[idx * 2 + 0] = (float)c;
    g_trig[idx * 2 + 1] = (float)s;
}

// ---------------------------------------------------------------------------
// tf32 GEMM, 64x64 warp tiles: block 128x128, 128 threads (2x2 warps),
// BK=16, 2-stage cp.async. Multi-output over blockIdx.z.
//   C_z[M,N] = A[M,K] @ W_z[N,K]^T + bias_z[N]
// ---------------------------------------------------------------------------
#define GBK  16
#define GSTR 20

__global__ __launch_bounds__(128, 2) void gemm_tf32_kernel(
    const float* __restrict__ A,
    const float* __restrict__ W0, const float* __restrict__ W1, const float* __restrict__ W2,
    const float* __restrict__ b0p, const float* __restrict__ b1p, const float* __restrict__ b2p,
    float* __restrict__ C0, float* __restrict__ C1, float* __restrict__ C2,
    int roundZ, int M, int N, int K)
{
    __shared__ float sm[2][2 * 128 * GSTR];   // per stage: A then W, 2560 each

    const int z = blockIdx.z;
    const float* W    = (z == 0) ? W0  : (z == 1) ? W1  : W2;
    const float* bias = (z == 0) ? b0p : (z == 1) ? b1p : b2p;
    float* C          = (z == 0) ? C0  : (z == 1) ? C1  : C2;
    const bool doRound = (z == roundZ);

    const int t    = threadIdx.x;       // 0..127
    const int lane = t & 31;
    const int warp = t >> 5;            // 0..3
    const int wm   = warp >> 1;
    const int wn   = warp & 1;
    const int bm   = blockIdx.y * 128;
    const int bn   = blockIdx.x * 128;

    const float* Ap = A + (size_t)(bm + t) * K;   // one row per thread
    const float* Wp = W + (size_t)(bn + t) * K;

    auto stage = [&](int it) {
        float* as = sm[it & 1];
        float* ws = as + 128 * GSTR;
        const float* ap = Ap + it * GBK;
        const float* wp = Wp + it * GBK;
#pragma unroll
        for (int c = 0; c < 4; ++c) {
            cp16(&as[t * GSTR + c * 4], ap + c * 4);
            cp16(&ws[t * GSTR + c * 4], wp + c * 4);
        }
        cp_commit();
    };

    float c[4][8][4];
#pragma unroll
    for (int mt = 0; mt < 4; mt++)
#pragma unroll
        for (int nt = 0; nt < 8; nt++)
#pragma unroll
            for (int j = 0; j < 4; j++) c[mt][nt][j] = 0.f;

    const int KITERS = K / GBK;   // 96
    stage(0);

    const int r0 = lane >> 2;
    const int kq = lane & 3;
    const int r_a = wm * 64 + r0;
    const int r_b = wn * 64 + r0;

    for (int it = 0; it < KITERS; ++it) {
        if (it + 1 < KITERS) { stage(it + 1); cp_wait<1>(); }
        else                 { cp_wait<0>(); }
        __syncthreads();

        const float* as = sm[it & 1];
        const float* ws = as + 128 * GSTR;

#pragma unroll
        for (int kt = 0; kt < 2; ++kt) {
            const int kc = kt * 8 + kq;
            unsigned a[4][4];
#pragma unroll
            for (int mt = 0; mt < 4; ++mt) {
                int r = r_a + mt * 16;
                a[mt][0] = fu(as[r * GSTR + kc]);
                a[mt][1] = fu(as[(r + 8) * GSTR + kc]);
                a[mt][2] = fu(as[r * GSTR + kc + 4]);
                a[mt][3] = fu(as[(r + 8) * GSTR + kc + 4]);
            }
#pragma unroll
            for (int nt = 0; nt < 8; ++nt) {
                int n = r_b + nt * 8;
                unsigned bb0 = fu(ws[n * GSTR + kc]);
                unsigned bb1 = fu(ws[n * GSTR + kc + 4]);
#pragma unroll
                for (int mt = 0; mt < 4; ++mt)
                    mma_tf32(c[mt][nt], a[mt], bb0, bb1);
            }
        }
        __syncthreads();
    }

    // Epilogue
#pragma unroll
    for (int mt = 0; mt < 4; ++mt) {
        int row = bm + wm * 64 + mt * 16 + r0;
#pragma unroll
        for (int nt = 0; nt < 8; ++nt) {
            int col = bn + wn * 64 + nt * 8 + 2 * kq;
            float bb0 = bias[col], bb1 = bias[col + 1];
            float v0 = c[mt][nt][0] + bb0, v1 = c[mt][nt][1] + bb1;
            float v2 = c[mt][nt][2] + bb0, v3 = c[mt][nt][3] + bb1;
            if (doRound) {
                v0 = to_tf32(v0); v1 = to_tf32(v1);
                v2 = to_tf32(v2); v3 = to_tf32(v3);
            }
            *(float2*)&C[(size_t)row * N + col]       = make_float2(v0, v1);
            *(float2*)&C[(size_t)(row + 8) * N + col] = make_float2(v2, v3);
        }
    }
}

// ---------------------------------------------------------------------------
// Fused RMSNorm + RoPE for q AND k in one launch: grid (SEQ, 2).
// Output tf32-rounded.
// ---------------------------------------------------------------------------
__global__ __launch_bounds__(256) void rmsnorm_rope_kernel(
    float* __restrict__ Xq, float* __restrict__ Xk,
    const float* __restrict__ gqv, const float* __restrict__ gkv)
{
    __shared__ float sh[DIM];
    __shared__ float red[8];
    __shared__ float s_r;

    const int s = blockIdx.x;
    const int which = blockIdx.y;
    float* X = which ? Xk : Xq;
    const float* g = which ? gkv : gqv;

    const int t = threadIdx.x;
    float* row = X + (size_t)s * DIM;

    float ss = 0.f;
    for (int i = t; i < DIM; i += 256) {
        float v = row[i];
        sh[i] = v;
        ss += v * v;
    }
#pragma unroll
    for (int off = 16; off > 0; off >>= 1)
        ss += __shfl_xor_sync(0xFFFFFFFFu, ss, off);
    if ((t & 31) == 0) red[t >> 5] = ss;
    __syncthreads();
    if (t == 0) {
        float tot = 0.f;
#pragma unroll
        for (int w = 0; w < 8; w++) tot += red[w];
        s_r = rsqrtf(tot / (float)DIM + EPS);
    }
    __syncthreads();
    const float r = s_r;

    for (int p = t; p < DIM / 2; p += 256) {
        int f0 = 2 * p, f1 = 2 * p + 1;
        int j = p & 63;
        float c  = g_trig[((size_t)s * 64 + j) * 2 + 0];
        float sn = g_trig[((size_t)s * 64 + j) * 2 + 1];
        float v0 = sh[f0] * r * g[f0];
        float v1 = sh[f1] * r * g[f1];
        row[f0] = to_tf32(v0 * c - v1 * sn);
        row[f1] = to_tf32(v0 * sn + v1 * c);
    }
}

// ---------------------------------------------------------------------------
// Repack K and V into fragment-order global layouts for the flash kernel.
//   kf[h][s][fperm(d)]           (column permute within each head)
//   vf[h][kb][kt][d][slot]       (transpose; slot = frag pair order of k%8)
// ---------------------------------------------------------------------------
__global__ __launch_bounds__(256) void repack_kernel(void) {
    int idx = blockIdx.x * blockDim.x + threadIdx.x;   // over SEQ*DIM/4
    if (idx >= SEQ * DIM / 4) return;
    int s  = idx / (DIM / 4);
    int c4 = (idx - s * (DIM / 4)) * 4;
    int h  = c4 >> 7;
    int d  = c4 & 127;

    float4 kv = *(const float4*)&g_k[(size_t)s * DIM + c4];
    float4 vv = *(const float4*)&g_v[(size_t)s * DIM + c4];

    // K: [h][s][fperm(d)]
    float* kdst = &g_kf[((size_t)h * SEQ + s) * HDIM];
    kdst[fperm(d + 0)] = kv.x;
    kdst[fperm(d + 1)] = kv.y;
    kdst[fperm(d + 2)] = kv.z;
    kdst[fperm(d + 3)] = kv.w;

    // V: [h][kb][kt][d][slot]
    int kb = s >> 5, kt = (s >> 3) & 3, k8 = s & 7;
    int slot = (k8 & 3) * 2 + (k8 >> 2);
    float* vdst = &g_vf[(((size_t)(h * 128 + kb)) * 4 + kt) * 1024 + slot];
    vdst[(d + 0) * 8] = vv.x;
    vdst[(d + 1) * 8] = vv.y;
    vdst[(d + 2) * 8] = vv.z;
    vdst[(d + 3) * 8] = vv.w;
}

// ---------------------------------------------------------------------------
// tf32 flash attention, fragment-order K/V (all B-fragment loads are LDS.64).
// 128 threads (4 warps), BQ=64 (16 rows/warp), BK=32, cp.async double buffer.
// ---------------------------------------------------------------------------
#define KS_STRIDE 136          // K smem row stride (keys x dims)
#define VT_STRIDE 1032         // V smem per-kt stride ([kt][d][slot])
#define PS_STRIDE 36
#define FA_SMEM_FLOATS (2 * 32 * KS_STRIDE + 2 * 4 * VT_STRIDE + 64 * PS_STRIDE)
#define FA_SMEM_BYTES  (FA_SMEM_FLOATS * 4)    // 77056

__global__ __launch_bounds__(128, 2) void flash_tf32_kernel(
    const float* __restrict__ Q, const float* __restrict__ Kf,
    const float* __restrict__ Vf, float* __restrict__ O)
{
    extern __shared__ float sm[];
    float* Kb[2];
    float* Vb[2];
    Kb[0] = sm;
    Kb[1] = Kb[0] + 32 * KS_STRIDE;
    Vb[0] = Kb[1] + 32 * KS_STRIDE;
    Vb[1] = Vb[0] + 4 * VT_STRIDE;
    float* Ps = Vb[1] + 4 * VT_STRIDE;

    const int h    = blockIdx.y;
    const int qb   = blockIdx.x;
    const int t    = threadIdx.x;
    const int lane = t & 31;
    const int warp = t >> 5;
    const int r0   = lane >> 2;
    const int qc   = lane & 3;
    const float scale = 0.08838834764831845f;   // 1/sqrt(128)

    // ---- Stage Q tile (normal layout; rows 0..31 -> Kb[0], 32..63 -> Kb[1]) ----
    {
        const float* src = Q + (size_t)(qb * 64) * DIM + h * HDIM;
        for (int i = t; i < 64 * 32; i += 128) {
            int r = i >> 5, c4 = (i & 31) * 4;
            float4 v = *(const float4*)&src[(size_t)r * DIM + c4];
            *(float4*)(Kb[r >> 5] + (r & 31) * KS_STRIDE + c4) = v;
        }
    }
    __syncthreads();

    unsigned qa[16][4];
    {
        const float* qbuf = Kb[warp >> 1];
        const int rb = (warp * 16 + r0) & 31;
#pragma unroll
        for (int kt = 0; kt < 16; ++kt) {
            int kc = kt * 8 + qc;
            qa[kt][0] = fu(qbuf[rb * KS_STRIDE + kc]);
            qa[kt][1] = fu(qbuf[(rb + 8) * KS_STRIDE + kc]);
            qa[kt][2] = fu(qbuf[rb * KS_STRIDE + kc + 4]);
            qa[kt][3] = fu(qbuf[(rb + 8) * KS_STRIDE + kc + 4]);
        }
    }
    __syncthreads();

    // ---- cp.async stage: K rows (fragment-permuted cols), V contiguous ----
    auto stage_kv = [&](int kb) {
        float* dk = Kb[kb & 1];
        float* dv = Vb[kb & 1];
        const float* ks = Kf + ((size_t)h * SEQ + kb * 32) * HDIM;
        const float* vs = Vf + ((size_t)(h * 128 + kb)) * 4096;
        for (int i = t; i < 1024; i += 128) {
            int r = i >> 5, c4 = (i & 31) * 4;
            cp16(&dk[r * KS_STRIDE + c4], &ks[r * HDIM + c4]);
        }
        for (int i = t; i < 1024; i += 128) {
            int kt = i >> 8, w = (i & 255) * 4;
            cp16(&dv[kt * VT_STRIDE + w], &vs[i * 4]);
        }
        cp_commit();
    };

    stage_kv(0);
    stage_kv(1);

    float o[16][4];
#pragma unroll
    for (int nt = 0; nt < 16; ++nt)
#pragma unroll
        for (int j = 0; j < 4; ++j) o[nt][j] = 0.f;

    float m0 = -1e30f, m1 = -1e30f, l0 = 0.f, l1 = 0.f;
    const int prow = warp * 16 + r0;
    const int NT = SEQ / 32;   // 128

    for (int kb = 0; kb < NT; ++kb) {
        if (kb + 1 < NT) cp_wait<1>(); else cp_wait<0>();
        __syncthreads();

        const float* Ks = Kb[kb & 1];
        const float* Vs = Vb[kb & 1];

        // ---- S = Q @ K^T (per warp: 16 x 32); B-frag = one LDS.64 ----
        float s[4][4];
#pragma unroll
        for (int nt = 0; nt < 4; ++nt)
#pragma unroll
            for (int j = 0; j < 4; ++j) s[nt][j] = 0.f;

#pragma unroll
        for (int nt = 0; nt < 4; ++nt) {
            const int nbase = (nt * 8 + r0) * KS_STRIDE + qc * 2;
#pragma unroll
            for (int kt = 0; kt < 16; ++kt) {
                float2 bv = *(const float2*)&Ks[nbase + kt * 8];
                mma_tf32(s[nt], qa[kt], fu(bv.x), fu(bv.y));
            }
        }

        // ---- Online softmax ----
        float mx0 = -1e30f, mx1 = -1e30f;
#pragma unroll
        for (int nt = 0; nt < 4; ++nt) {
            mx0 = fmaxf(mx0, fmaxf(s[nt][0], s[nt][1]));
            mx1 = fmaxf(mx1, fmaxf(s[nt][2], s[nt][3]));
        }
        mx0 = fmaxf(mx0, __shfl_xor_sync(0xFFFFFFFFu, mx0, 1));
        mx0 = fmaxf(mx0, __shfl_xor_sync(0xFFFFFFFFu, mx0, 2));
        mx1 = fmaxf(mx1, __shfl_xor_sync(0xFFFFFFFFu, mx1, 1));
        mx1 = fmaxf(mx1, __shfl_xor_sync(0xFFFFFFFFu, mx1, 2));

        float nm0 = fmaxf(m0, mx0 * scale);
        float nm1 = fmaxf(m1, mx1 * scale);
        float corr0 = __expf(m0 - nm0);
        float corr1 = __expf(m1 - nm1);

        float sum0 = 0.f, sum1 = 0.f;
#pragma unroll
        for (int nt = 0; nt < 4; ++nt) {
            s[nt][0] = __expf(s[nt][0] * scale - nm0);
            s[nt][1] = __expf(s[nt][1] * scale - nm0);
            s[nt][2] = __expf(s[nt][2] * scale - nm1);
            s[nt][3] = __expf(s[nt][3] * scale - nm1);
            sum0 += s[nt][0] + s[nt][1];
            sum1 += s[nt][2] + s[nt][3];
        }
        sum0 += __shfl_xor_sync(0xFFFFFFFFu, sum0, 1);
        sum0 += __shfl_xor_sync(0xFFFFFFFFu, sum0, 2);
        sum1 += __shfl_xor_sync(0xFFFFFFFFu, sum1, 1);
        sum1 += __shfl_xor_sync(0xFFFFFFFFu, sum1, 2);

        l0 = l0 * corr0 + sum0;
        l1 = l1 * corr1 + sum1;
        m0 = nm0;
        m1 = nm1;

#pragma unroll
        for (int nt = 0; nt < 16; ++nt) {
            o[nt][0] *= corr0; o[nt][1] *= corr0;
            o[nt][2] *= corr1; o[nt][3] *= corr1;
        }

        // ---- P -> smem (warp-local rows), tf32-rounded ----
#pragma unroll
        for (int nt = 0; nt < 4; ++nt) {
            int pc = nt * 8 + 2 * qc;
            *(float2*)&Ps[prow * PS_STRIDE + pc] =
                make_float2(to_tf32(s[nt][0]), to_tf32(s[nt][1]));
            *(float2*)&Ps[(prow + 8) * PS_STRIDE + pc] =
                make_float2(to_tf32(s[nt][2]), to_tf32(s[nt][3]));
        }
        __syncwarp();

        // ---- O += P @ V ; V B-frag = one LDS.64 ----
#pragma unroll
        for (int kt = 0; kt < 4; ++kt) {
            unsigned a[4];
            int kc = kt * 8 + qc;
            a[0] = fu(Ps[prow * PS_STRIDE + kc]);
            a[1] = fu(Ps[(prow + 8) * PS_STRIDE + kc]);
            a[2] = fu(Ps[prow * PS_STRIDE + kc + 4]);
            a[3] = fu(Ps[(prow + 8) * PS_STRIDE + kc + 4]);
            const int vbase = kt * VT_STRIDE + r0 * 8 + qc * 2;
#pragma unroll
            for (int nt = 0; nt < 16; ++nt) {
                float2 bv = *(const float2*)&Vs[vbase + nt * 64];
                mma_tf32(o[nt], a, fu(bv.x), fu(bv.y));
            }
        }
        __syncthreads();
        if (kb + 2 < NT) stage_kv(kb + 2);
    }

    float inv0 = 1.f / l0, inv1 = 1.f / l1;
    int grow = qb * 64 + warp * 16 + r0;
#pragma unroll
    for (int nt = 0; nt < 16; ++nt) {
        int col = h * HDIM + nt * 8 + 2 * qc;
        *(float2*)&O[(size_t)grow * DIM + col] =
            make_float2(to_tf32(o[nt][0] * inv0), to_tf32(o[nt][1] * inv0));
        *(float2*)&O[(size_t)(grow + 8) * DIM + col] =
            make_float2(to_tf32(o[nt][2] * inv1), to_tf32(o[nt][3] * inv1));
    }
}

// ---------------------------------------------------------------------------
// Launch
// ---------------------------------------------------------------------------
extern "C" void kernel_launch(void* const* d_in, const int* in_sizes, int n_in,
                              void* d_out, int out_size)
{
    const float* x     = (const float*)d_in[0];
    const float* freqs = (const float*)d_in[1];
    const float* Wq    = (const float*)d_in[2];
    const float* bq    = (const float*)d_in[3];
    const float* Wk    = (const float*)d_in[4];
    const float* bk    = (const float*)d_in[5];
    const float* Wv    = (const float*)d_in[6];
    const float* bv    = (const float*)d_in[7];
    const float* Wo    = (const float*)d_in[8];
    const float* bo    = (const float*)d_in[9];
    const float* gq    = (const float*)d_in[10];
    const float* gk    = (const float*)d_in[11];
    float* out = (float*)d_out;

    float *q, *k, *v, *attn, *kf, *vf;
    cudaGetSymbolAddress((void**)&q,    g_q);
    cudaGetSymbolAddress((void**)&k,    g_k);
    cudaGetSymbolAddress((void**)&v,    g_v);
    cudaGetSymbolAddress((void**)&attn, g_attn);
    cudaGetSymbolAddress((void**)&kf,   g_kf);
    cudaGetSymbolAddress((void**)&vf,   g_vf);

    cudaFuncSetAttribute(flash_tf32_kernel,
                         cudaFuncAttributeMaxDynamicSharedMemorySize, FA_SMEM_BYTES);

    trig_kernel<<<(SEQ * 64 + 255) / 256, 256>>>(freqs);

    // Fused Q/K/V projection: one launch.
    dim3 qkv_grid(DIM / 128, SEQ / 128, 3);
    gemm_tf32_kernel<<<qkv_grid, 128>>>(
        x, Wq, Wk, Wv, bq, bk, bv, q, k, v,
        /*roundZ=*/2, SEQ, DIM, DIM);

    // RMSNorm+RoPE for q and k in one launch.
    rmsnorm_rope_kernel<<<dim3(SEQ, 2), 256>>>(q, k, gq, gk);

    // Repack K, V into fragment-order layouts.
    repack_kernel<<<(SEQ * DIM / 4 + 255) / 256, 256>>>();

    flash_tf32_kernel<<<dim3(SEQ / 64, NHEADS), 128, FA_SMEM_BYTES>>>(q, kf, vf, attn);

    // Output projection.
    dim3 o_grid(DIM / 128, SEQ / 128, 1);
    gemm_tf32_kernel<<<o_grid, 128>>>(
        attn, Wo, Wo, Wo, bo, bo, bo, out, out, out,
        /*roundZ=*/-1, SEQ, DIM, DIM);
}

// round 7
// speedup vs baseline: 1.7416x; 1.7416x over previous
#include <cuda_runtime.h>
#include <cuda_fp16.h>
#include <math.h>
#include <stdint.h>

// ---------------------------------------------------------------------------
// Problem constants (B=1, S=4096, DIM=1536, HEADS=12, HEAD_DIM=128)
// ---------------------------------------------------------------------------
#define SEQ    4096
#define DIM    1536
#define NHEADS 12
#define HDIM   128
#define EPS    1e-6f

// Scratch (allocation-free rule: __device__ globals)
__device__ __half g_xh[SEQ * DIM];
__device__ __half g_qh[SEQ * DIM];
__device__ __half g_kh[SEQ * DIM];
__device__ __half g_vh[SEQ * DIM];
__device__ __half g_attnh[SEQ * DIM];
__device__ __half g_wqh[DIM * DIM];
__device__ __half g_wkh[DIM * DIM];
__device__ __half g_wvh[DIM * DIM];
__device__ __half g_woh[DIM * DIM];
__device__ __half g_vt[NHEADS * HDIM * SEQ];   // V transposed: [h][d][s]
__device__ float  g_trig[SEQ * 64 * 2];        // cos,sin per (pos, pair)

// ---------------------------------------------------------------------------
// Helpers
// ---------------------------------------------------------------------------
__device__ __forceinline__ unsigned ld32h(const __half* p) {
    return *(const unsigned*)p;
}

// D += A*B, m16n8k16, fp16 inputs, f32 accumulate
__device__ __forceinline__ void mma_f16(float* d, const unsigned* a,
                                        unsigned b0, unsigned b1) {
    asm volatile(
        "mma.sync.aligned.m16n8k16.row.col.f32.f16.f16.f32 "
        "{%0,%1,%2,%3}, {%4,%5,%6,%7}, {%8,%9}, {%0,%1,%2,%3};\n"
        : "+f"(d[0]), "+f"(d[1]), "+f"(d[2]), "+f"(d[3])
        : "r"(a[0]), "r"(a[1]), "r"(a[2]), "r"(a[3]), "r"(b0), "r"(b1));
}

// ---------------------------------------------------------------------------
// Prep: fp32 -> fp16 conversion (vectorized)
// ---------------------------------------------------------------------------
__global__ __launch_bounds__(256) void to_half_kernel(
    const float* __restrict__ src, __half* __restrict__ dst, int n4)
{
    int i = blockIdx.x * blockDim.x + threadIdx.x;
    if (i >= n4) return;
    float4 v = ((const float4*)src)[i];
    __half2* d = (__half2*)dst;
    d[2 * i + 0] = __floats2half2_rn(v.x, v.y);
    d[2 * i + 1] = __floats2half2_rn(v.z, v.w);
}

// ---------------------------------------------------------------------------
// RoPE trig table with double-precision range reduction.
// ---------------------------------------------------------------------------
__global__ __launch_bounds__(256) void trig_kernel(const float* __restrict__ freqs) {
    int idx = blockIdx.x * blockDim.x + threadIdx.x;
    if (idx >= SEQ * 64) return;
    double a = (double)freqs[idx];
    double s, c;
    sincos(a, &s, &c);
    g_trig[idx * 2 + 0] = (float)c;
    g_trig[idx * 2 + 1] = (float)s;
}

// ---------------------------------------------------------------------------
// fp16 tensor-core GEMM, multi-output over blockIdx.z:
//   C_z[M,N] = A[M,K] @ W_z[N,K]^T + bias_z[N]
// BM=BN=128, BK=16, 256 threads (8 warps 4m x 2n), warp tile 32x64.
// Register-prefetch double buffer; smem stride 24 halfs (bank-conflict-free).
// HALF_OUT: write __half output (q/k/v), else float (final out).
// ---------------------------------------------------------------------------
#define GSH 24

template <int HALF_OUT>
__global__ __launch_bounds__(256, 2) void gemm_h_kernel(
    const __half* __restrict__ A,
    const __half* __restrict__ W0, const __half* __restrict__ W1,
    const __half* __restrict__ W2,
    const float* __restrict__ b0p, const float* __restrict__ b1p,
    const float* __restrict__ b2p,
    void* C0, void* C1, void* C2)
{
    __shared__ __half As[2][128 * GSH];
    __shared__ __half Ws[2][128 * GSH];

    const int z = blockIdx.z;
    const __half* W   = (z == 0) ? W0  : (z == 1) ? W1  : W2;
    const float* bias = (z == 0) ? b0p : (z == 1) ? b1p : b2p;
    void* C           = (z == 0) ? C0  : (z == 1) ? C1  : C2;

    const int t    = threadIdx.x;
    const int lane = t & 31;
    const int warp = t >> 5;
    const int wm   = warp >> 1;     // 0..3
    const int wn   = warp & 1;      // 0..1
    const int bm   = blockIdx.y * 128;
    const int bn   = blockIdx.x * 128;

    const int lrow = t >> 1;            // 0..127
    const int lc8  = (t & 1) * 8;       // 0 or 8

    const __half* Ap = A + (size_t)(bm + lrow) * DIM + lc8;
    const __half* Wp = W + (size_t)(bn + lrow) * DIM + lc8;

    float c[2][8][4];
#pragma unroll
    for (int mt = 0; mt < 2; mt++)
#pragma unroll
        for (int nt = 0; nt < 8; nt++)
#pragma unroll
            for (int j = 0; j < 4; j++) c[mt][nt][j] = 0.f;

    const int KITERS = DIM / 16;   // 96

    uint4 pa = *(const uint4*)Ap;
    uint4 pw = *(const uint4*)Wp;
    *(uint4*)&As[0][lrow * GSH + lc8] = pa;
    *(uint4*)&Ws[0][lrow * GSH + lc8] = pw;
    __syncthreads();

    const int r0  = lane >> 2;
    const int kq  = lane & 3;
    const int r_a = wm * 32 + r0;
    const int r_b = wn * 64 + r0;

    for (int it = 0; it < KITERS; ++it) {
        const int cur = it & 1;
        if (it + 1 < KITERS) {
            pa = *(const uint4*)(Ap + (it + 1) * 16);
            pw = *(const uint4*)(Wp + (it + 1) * 16);
        }

        const __half* as = As[cur];
        const __half* ws = Ws[cur];

        unsigned a[2][4];
#pragma unroll
        for (int mt = 0; mt < 2; ++mt) {
            int r = r_a + mt * 16;
            a[mt][0] = ld32h(&as[r * GSH + 2 * kq]);
            a[mt][1] = ld32h(&as[(r + 8) * GSH + 2 * kq]);
            a[mt][2] = ld32h(&as[r * GSH + 2 * kq + 8]);
            a[mt][3] = ld32h(&as[(r + 8) * GSH + 2 * kq + 8]);
        }
#pragma unroll
        for (int nt = 0; nt < 8; ++nt) {
            int n = r_b + nt * 8;
            unsigned bb0 = ld32h(&ws[n * GSH + 2 * kq]);
            unsigned bb1 = ld32h(&ws[n * GSH + 2 * kq + 8]);
            mma_f16(c[0][nt], a[0], bb0, bb1);
            mma_f16(c[1][nt], a[1], bb0, bb1);
        }

        if (it + 1 < KITERS) {
            *(uint4*)&As[cur ^ 1][lrow * GSH + lc8] = pa;
            *(uint4*)&Ws[cur ^ 1][lrow * GSH + lc8] = pw;
        }
        __syncthreads();
    }

    // Epilogue: bias + store
#pragma unroll
    for (int mt = 0; mt < 2; ++mt) {
#pragma unroll
        for (int nt = 0; nt < 8; ++nt) {
            int row = bm + wm * 32 + mt * 16 + r0;
            int col = bn + wn * 64 + nt * 8 + 2 * kq;
            float bb0 = bias[col], bb1 = bias[col + 1];
            float v0 = c[mt][nt][0] + bb0, v1 = c[mt][nt][1] + bb1;
            float v2 = c[mt][nt][2] + bb0, v3 = c[mt][nt][3] + bb1;
            if (HALF_OUT) {
                __half2* Ch = (__half2*)C;
                Ch[((size_t)row * DIM + col) >> 1]       = __floats2half2_rn(v0, v1);
                Ch[((size_t)(row + 8) * DIM + col) >> 1] = __floats2half2_rn(v2, v3);
            } else {
                float* Cf = (float*)C;
                *(float2*)&Cf[(size_t)row * DIM + col]       = make_float2(v0, v1);
                *(float2*)&Cf[(size_t)(row + 8) * DIM + col] = make_float2(v2, v3);
            }
        }
    }
}

// ---------------------------------------------------------------------------
// Fused RMSNorm + RoPE for q AND k (fp16 in/out, fp32 math): grid (SEQ, 2).
// ---------------------------------------------------------------------------
__global__ __launch_bounds__(256) void rmsnorm_rope_kernel(
    __half* __restrict__ Xq, __half* __restrict__ Xk,
    const float* __restrict__ gqv, const float* __restrict__ gkv)
{
    __shared__ float sh[DIM];
    __shared__ float red[8];
    __shared__ float s_r;

    const int s = blockIdx.x;
    const int which = blockIdx.y;
    __half* X = which ? Xk : Xq;
    const float* g = which ? gkv : gqv;

    const int t = threadIdx.x;
    __half2* row = (__half2*)(X + (size_t)s * DIM);

    float ss = 0.f;
    for (int i = t; i < DIM / 2; i += 256) {
        float2 f = __half22float2(row[i]);
        sh[2 * i]     = f.x;
        sh[2 * i + 1] = f.y;
        ss += f.x * f.x + f.y * f.y;
    }
#pragma unroll
    for (int off = 16; off > 0; off >>= 1)
        ss += __shfl_xor_sync(0xFFFFFFFFu, ss, off);
    if ((t & 31) == 0) red[t >> 5] = ss;
    __syncthreads();
    if (t == 0) {
        float tot = 0.f;
#pragma unroll
        for (int w = 0; w < 8; w++) tot += red[w];
        s_r = rsqrtf(tot / (float)DIM + EPS);
    }
    __syncthreads();
    const float r = s_r;

    for (int p = t; p < DIM / 2; p += 256) {
        int j = p & 63;
        float c  = g_trig[((size_t)s * 64 + j) * 2 + 0];
        float sn = g_trig[((size_t)s * 64 + j) * 2 + 1];
        float v0 = sh[2 * p] * r * g[2 * p];
        float v1 = sh[2 * p + 1] * r * g[2 * p + 1];
        row[p] = __floats2half2_rn(v0 * c - v1 * sn, v0 * sn + v1 * c);
    }
}

// ---------------------------------------------------------------------------
// Transpose V: g_vh[s][h*128+d] -> g_vt[h][d][s].  Tiles 64s x 64d.
// ---------------------------------------------------------------------------
__global__ __launch_bounds__(256) void transpose_v_kernel(void) {
    __shared__ __half tile[64][80];
    const int t  = threadIdx.x;
    const int h  = blockIdx.y >> 1;
    const int d0 = (blockIdx.y & 1) * 64;
    const int s0 = blockIdx.x * 64;

    for (int i = t; i < 512; i += 256) {
        int r = i >> 3, c8 = (i & 7) * 8;     // r: s-row, c8: d-col
        uint4 v = *(const uint4*)&g_vh[(size_t)(s0 + r) * DIM + h * HDIM + d0 + c8];
        *(uint4*)&tile[r][c8] = v;
    }
    __syncthreads();
    for (int i = t; i < 512; i += 256) {
        int r = i >> 3, c8 = (i & 7) * 8;     // r: d-row, c8: s-col
        __half tmp[8];
#pragma unroll
        for (int j = 0; j < 8; ++j) tmp[j] = tile[c8 + j][r];
        *(uint4*)&g_vt[(size_t)(h * HDIM + d0 + r) * SEQ + s0 + c8] = *(uint4*)tmp;
    }
}

// ---------------------------------------------------------------------------
// fp16 flash attention. 128 threads (4 warps), BQ=64 (16 rows/warp), BK=64.
// Q fragments in registers (32 regs). K natural [key][d]; V via Vt [d][key].
// fp32 softmax and O accumulators. Output fp16 (feeds O-projection GEMM).
// ---------------------------------------------------------------------------
#define KSH 136
#define VSH 72
#define PSH 72
#define FA_SMEM_BYTES ((64 * KSH + 128 * VSH + 64 * PSH) * 2)   // 45056

__global__ __launch_bounds__(128, 2) void flash_h_kernel(
    const __half* __restrict__ Q, const __half* __restrict__ Kg,
    const __half* __restrict__ Vt, __half* __restrict__ O)
{
    extern __shared__ __half smh[];
    __half* Ks = smh;                    // 64 x 136
    __half* Vs = Ks + 64 * KSH;          // 128 x 72 (d-major)
    __half* Ps = Vs + 128 * VSH;         // 64 x 72

    const int h    = blockIdx.y;
    const int qb   = blockIdx.x;
    const int t    = threadIdx.x;
    const int lane = t & 31;
    const int warp = t >> 5;
    const int r0   = lane >> 2;
    const int qc   = lane & 3;
    const float scale = 0.08838834764831845f;   // 1/sqrt(128)

    // ---- Stage Q tile into Ks, pull A-fragments to registers ----
    {
        const __half* src = Q + (size_t)(qb * 64) * DIM + h * HDIM;
        for (int i = t; i < 64 * 16; i += 128) {
            int r = i >> 4, c8 = (i & 15) * 8;
            *(uint4*)&Ks[r * KSH + c8] = *(const uint4*)&src[(size_t)r * DIM + c8];
        }
    }
    __syncthreads();

    unsigned qa[8][4];
    {
        const int rb = warp * 16 + r0;
#pragma unroll
        for (int kt = 0; kt < 8; ++kt) {
            int kc = kt * 16 + 2 * qc;
            qa[kt][0] = ld32h(&Ks[rb * KSH + kc]);
            qa[kt][1] = ld32h(&Ks[(rb + 8) * KSH + kc]);
            qa[kt][2] = ld32h(&Ks[rb * KSH + kc + 8]);
            qa[kt][3] = ld32h(&Ks[(rb + 8) * KSH + kc + 8]);
        }
    }
    __syncthreads();

    float o[16][4];
#pragma unroll
    for (int nt = 0; nt < 16; ++nt)
#pragma unroll
        for (int j = 0; j < 4; ++j) o[nt][j] = 0.f;

    float m0 = -1e30f, m1 = -1e30f, l0 = 0.f, l1 = 0.f;
    const int prow = warp * 16 + r0;

    for (int kb = 0; kb < SEQ / 64; ++kb) {
        __syncthreads();

        // ---- Stage K tile [64 keys][128 d] and Vt tile [128 d][64 keys] ----
        {
            const __half* ksrc = Kg + (size_t)(kb * 64) * DIM + h * HDIM;
            for (int i = t; i < 64 * 16; i += 128) {
                int r = i >> 4, c8 = (i & 15) * 8;
                *(uint4*)&Ks[r * KSH + c8] = *(const uint4*)&ksrc[(size_t)r * DIM + c8];
            }
            const __half* vsrc = Vt + (size_t)h * HDIM * SEQ + kb * 64;
            for (int i = t; i < 128 * 16; i += 128) {
                int r = i >> 4, c4 = (i & 15) * 4;
                *(uint2*)&Vs[r * VSH + c4] = *(const uint2*)&vsrc[(size_t)r * SEQ + c4];
            }
        }
        __syncthreads();

        // ---- S = Q @ K^T (per warp: 16 x 64) ----
        float s[8][4];
#pragma unroll
        for (int nt = 0; nt < 8; ++nt)
#pragma unroll
            for (int j = 0; j < 4; ++j) s[nt][j] = 0.f;

#pragma unroll
        for (int nt = 0; nt < 8; ++nt) {
            const int nb = (nt * 8 + r0) * KSH + 2 * qc;
#pragma unroll
            for (int kt = 0; kt < 8; ++kt) {
                unsigned b0 = ld32h(&Ks[nb + kt * 16]);
                unsigned b1 = ld32h(&Ks[nb + kt * 16 + 8]);
                mma_f16(s[nt], qa[kt], b0, b1);
            }
        }

        // ---- Online softmax ----
        float mx0 = -1e30f, mx1 = -1e30f;
#pragma unroll
        for (int nt = 0; nt < 8; ++nt) {
            mx0 = fmaxf(mx0, fmaxf(s[nt][0], s[nt][1]));
            mx1 = fmaxf(mx1, fmaxf(s[nt][2], s[nt][3]));
        }
        mx0 = fmaxf(mx0, __shfl_xor_sync(0xFFFFFFFFu, mx0, 1));
        mx0 = fmaxf(mx0, __shfl_xor_sync(0xFFFFFFFFu, mx0, 2));
        mx1 = fmaxf(mx1, __shfl_xor_sync(0xFFFFFFFFu, mx1, 1));
        mx1 = fmaxf(mx1, __shfl_xor_sync(0xFFFFFFFFu, mx1, 2));

        float nm0 = fmaxf(m0, mx0 * scale);
        float nm1 = fmaxf(m1, mx1 * scale);
        float corr0 = __expf(m0 - nm0);
        float corr1 = __expf(m1 - nm1);

        float sum0 = 0.f, sum1 = 0.f;
#pragma unroll
        for (int nt = 0; nt < 8; ++nt) {
            s[nt][0] = __expf(s[nt][0] * scale - nm0);
            s[nt][1] = __expf(s[nt][1] * scale - nm0);
            s[nt][2] = __expf(s[nt][2] * scale - nm1);
            s[nt][3] = __expf(s[nt][3] * scale - nm1);
            sum0 += s[nt][0] + s[nt][1];
            sum1 += s[nt][2] + s[nt][3];
        }
        sum0 += __shfl_xor_sync(0xFFFFFFFFu, sum0, 1);
        sum0 += __shfl_xor_sync(0xFFFFFFFFu, sum0, 2);
        sum1 += __shfl_xor_sync(0xFFFFFFFFu, sum1, 1);
        sum1 += __shfl_xor_sync(0xFFFFFFFFu, sum1, 2);

        l0 = l0 * corr0 + sum0;
        l1 = l1 * corr1 + sum1;
        m0 = nm0;
        m1 = nm1;

#pragma unroll
        for (int nt = 0; nt < 16; ++nt) {
            o[nt][0] *= corr0; o[nt][1] *= corr0;
            o[nt][2] *= corr1; o[nt][3] *= corr1;
        }

        // ---- P -> smem fp16 (warp-local rows) ----
#pragma unroll
        for (int nt = 0; nt < 8; ++nt) {
            int pc = nt * 8 + 2 * qc;
            *(__half2*)&Ps[prow * PSH + pc] = __floats2half2_rn(s[nt][0], s[nt][1]);
            *(__half2*)&Ps[(prow + 8) * PSH + pc] = __floats2half2_rn(s[nt][2], s[nt][3]);
        }
        __syncwarp();

        // ---- O += P @ V (Vt: B-frag = one LDS.32) ----
#pragma unroll
        for (int kt = 0; kt < 4; ++kt) {
            unsigned a[4];
            int kc = kt * 16 + 2 * qc;
            a[0] = ld32h(&Ps[prow * PSH + kc]);
            a[1] = ld32h(&Ps[(prow + 8) * PSH + kc]);
            a[2] = ld32h(&Ps[prow * PSH + kc + 8]);
            a[3] = ld32h(&Ps[(prow + 8) * PSH + kc + 8]);
#pragma unroll
            for (int nt = 0; nt < 16; ++nt) {
                const int nb = (nt * 8 + r0) * VSH + kt * 16 + 2 * qc;
                unsigned b0 = ld32h(&Vs[nb]);
                unsigned b1 = ld32h(&Vs[nb + 8]);
                mma_f16(o[nt], a, b0, b1);
            }
        }
    }

    // ---- Epilogue: normalize, fp16 store ----
    float inv0 = 1.f / l0, inv1 = 1.f / l1;
    int grow = qb * 64 + warp * 16 + r0;
#pragma unroll
    for (int nt = 0; nt < 16; ++nt) {
        int col = h * HDIM + nt * 8 + 2 * qc;
        *(__half2*)&O[(size_t)grow * DIM + col] =
            __floats2half2_rn(o[nt][0] * inv0, o[nt][1] * inv0);
        *(__half2*)&O[(size_t)(grow + 8) * DIM + col] =
            __floats2half2_rn(o[nt][2] * inv1, o[nt][3] * inv1);
    }
}

// ---------------------------------------------------------------------------
// Launch
// ---------------------------------------------------------------------------
extern "C" void kernel_launch(void* const* d_in, const int* in_sizes, int n_in,
                              void* d_out, int out_size)
{
    const float* x     = (const float*)d_in[0];
    const float* freqs = (const float*)d_in[1];
    const float* Wq    = (const float*)d_in[2];
    const float* bq    = (const float*)d_in[3];
    const float* Wk    = (const float*)d_in[4];
    const float* bk    = (const float*)d_in[5];
    const float* Wv    = (const float*)d_in[6];
    const float* bv    = (const float*)d_in[7];
    const float* Wo    = (const float*)d_in[8];
    const float* bo    = (const float*)d_in[9];
    const float* gq    = (const float*)d_in[10];
    const float* gk    = (const float*)d_in[11];
    float* out = (float*)d_out;

    __half *xh, *qh, *kh, *vh, *attnh, *wqh, *wkh, *wvh, *woh, *vt;
    cudaGetSymbolAddress((void**)&xh,    g_xh);
    cudaGetSymbolAddress((void**)&qh,    g_qh);
    cudaGetSymbolAddress((void**)&kh,    g_kh);
    cudaGetSymbolAddress((void**)&vh,    g_vh);
    cudaGetSymbolAddress((void**)&attnh, g_attnh);
    cudaGetSymbolAddress((void**)&wqh,   g_wqh);
    cudaGetSymbolAddress((void**)&wkh,   g_wkh);
    cudaGetSymbolAddress((void**)&wvh,   g_wvh);
    cudaGetSymbolAddress((void**)&woh,   g_woh);
    cudaGetSymbolAddress((void**)&vt,    g_vt);

    cudaFuncSetAttribute(flash_h_kernel,
                         cudaFuncAttributeMaxDynamicSharedMemorySize, FA_SMEM_BYTES);

    // Prep: trig + fp16 conversion of x and weights.
    trig_kernel<<<(SEQ * 64 + 255) / 256, 256>>>(freqs);
    const int xn4 = SEQ * DIM / 4, wn4 = DIM * DIM / 4;
    to_half_kernel<<<(xn4 + 255) / 256, 256>>>(x,  xh, xn4);
    to_half_kernel<<<(wn4 + 255) / 256, 256>>>(Wq, wqh, wn4);
    to_half_kernel<<<(wn4 + 255) / 256, 256>>>(Wk, wkh, wn4);
    to_half_kernel<<<(wn4 + 255) / 256, 256>>>(Wv, wvh, wn4);
    to_half_kernel<<<(wn4 + 255) / 256, 256>>>(Wo, woh, wn4);

    // Fused Q/K/V projection (fp16 in/out).
    dim3 qkv_grid(DIM / 128, SEQ / 128, 3);
    gemm_h_kernel<1><<<qkv_grid, 256>>>(
        xh, wqh, wkh, wvh, bq, bk, bv, qh, kh, vh);

    // RMSNorm+RoPE for q and k.
    rmsnorm_rope_kernel<<<dim3(SEQ, 2), 256>>>(qh, kh, gq, gk);

    // Transpose V for the PV GEMM.
    transpose_v_kernel<<<dim3(SEQ / 64, 2 * NHEADS), 256>>>();

    flash_h_kernel<<<dim3(SEQ / 64, NHEADS), 128, FA_SMEM_BYTES>>>(qh, kh, vt, attnh);

    // Output projection (fp32 out).
    dim3 o_grid(DIM / 128, SEQ / 128, 1);
    gemm_h_kernel<0><<<o_grid, 256>>>(
        attnh, woh, woh, woh, bo, bo, bo, out, out, out);
}